// round 2
// baseline (speedup 1.0000x reference)
#include <cuda_runtime.h>

#define NBX 168
#define NBY 480
#define NBL 6
#define EXT 2
#define WW 5
#define NBINS_XY (NBX * NBY)
#define NBINS (NBX * NBY * NBL)          // 483840
#define INV_SQRT2 0.70710678118654752440f
#define INV_CAP (1.0f / 16.0f)

__device__ float g_dem[NBINS];
__device__ float g_compat[NBINS];

// ---------------------------------------------------------------------------
// Phase 0: zero demand map + output buffer
// ---------------------------------------------------------------------------
__global__ void zero_kernel(float* __restrict__ out, int out_n) {
    int i = blockIdx.x * blockDim.x + threadIdx.x;
    if (i < NBINS) g_dem[i] = 0.0f;
    if (i < out_n) out[i] = 0.0f;
}

// Compute the 5 axis weights via the erf chain: e_k = erf((b0+k - c)/sqrt2),
// g[k] = 0.5*(e_{k+1}-e_k), zeroed when bin out of range.
__device__ __forceinline__ void axis_weights(float c, int nb, int& b0, float* g) {
    b0 = (int)floorf(c) - EXT;
    float ep = erff(((float)b0 - c) * INV_SQRT2);
#pragma unroll
    for (int k = 0; k < WW; k++) {
        float e = erff(((float)(b0 + k + 1) - c) * INV_SQRT2);
        int b = b0 + k;
        g[k] = (b >= 0 && b < nb) ? 0.5f * (e - ep) : 0.0f;
        ep = e;
    }
}

// ---------------------------------------------------------------------------
// Phase 1: scatter-add area * (gX outer gY) into demand map
// ---------------------------------------------------------------------------
__global__ void scatter_kernel(const float* __restrict__ pos,
                               const float* __restrict__ nsx,
                               const float* __restrict__ nsy,
                               const int*   __restrict__ lidx,
                               const int*   __restrict__ ltype,
                               int Lnum, int n) {
    int l = blockIdx.x * blockDim.x + threadIdx.x;
    if (l >= Lnum) return;
    int idx = lidx[l];
    float sx = nsx[idx];
    float sy = nsy[idx];
    float cx = pos[idx]     + 0.5f * sx;
    float cy = pos[n + idx] + 0.5f * sy;
    float area = sx * sy;
    int lt = ltype[idx];

    int bx0, by0;
    float gx[WW], gy[WW];
    axis_weights(cx, NBX, bx0, gx);
    axis_weights(cy, NBY, by0, gy);

#pragma unroll
    for (int i = 0; i < WW; i++) {
        float axi = area * gx[i];
        if (axi == 0.0f) continue;
        int rowbase = ((bx0 + i) * NBY + by0) * NBL + lt;
#pragma unroll
        for (int j = 0; j < WW; j++) {
            float v = axi * gy[j];
            if (v != 0.0f) atomicAdd(&g_dem[rowbase + j * NBL], v);
        }
    }
}

// ---------------------------------------------------------------------------
// Phase 2: compat[x,y,t] = sum_l dem[x,y,l] * frac[t,l]
// ---------------------------------------------------------------------------
__global__ void compat_kernel(const int* __restrict__ frac) {
    int bin = blockIdx.x * blockDim.x + threadIdx.x;
    if (bin >= NBINS_XY) return;
    float d[NBL];
#pragma unroll
    for (int l = 0; l < NBL; l++) d[l] = g_dem[bin * NBL + l];
#pragma unroll
    for (int t = 0; t < NBL; t++) {
        float s = 0.0f;
#pragma unroll
        for (int l = 0; l < NBL; l++)
            s += (float)__ldg(&frac[t * NBL + l]) * d[l];
        g_compat[bin * NBL + t] = s;
    }
}

// ---------------------------------------------------------------------------
// Phase 3: gather compat under each instance window, write output
// ---------------------------------------------------------------------------
__global__ void gather_kernel(const float* __restrict__ pos,
                              const float* __restrict__ nsx,
                              const float* __restrict__ nsy,
                              const int*   __restrict__ lidx,
                              const int*   __restrict__ ltype,
                              float* __restrict__ out,
                              int Lnum, int n) {
    int l = blockIdx.x * blockDim.x + threadIdx.x;
    if (l >= Lnum) return;
    int idx = lidx[l];
    float sx = nsx[idx];
    float sy = nsy[idx];
    float cx = pos[idx]     + 0.5f * sx;
    float cy = pos[n + idx] + 0.5f * sy;
    int lt = ltype[idx];

    int bx0, by0;
    float gx[WW], gy[WW];
    axis_weights(cx, NBX, bx0, gx);
    axis_weights(cy, NBY, by0, gy);

    float s = 0.0f;
#pragma unroll
    for (int i = 0; i < WW; i++) {
        if (gx[i] == 0.0f) continue;
        int rowbase = ((bx0 + i) * NBY + by0) * NBL + lt;
        float sj = 0.0f;
#pragma unroll
        for (int j = 0; j < WW; j++) {
            if (gy[j] != 0.0f)
                sj += gy[j] * g_compat[rowbase + j * NBL];
        }
        s += gx[i] * sj;
    }
    out[idx] = s * INV_CAP;
}

// ---------------------------------------------------------------------------
extern "C" void kernel_launch(void* const* d_in, const int* in_sizes, int n_in,
                              void* d_out, int out_size) {
    const float* pos   = (const float*)d_in[0];
    const float* nsx   = (const float*)d_in[1];
    const float* nsy   = (const float*)d_in[2];
    const int*   lidx  = (const int*)d_in[3];
    const int*   ltype = (const int*)d_in[4];
    const int*   frac  = (const int*)d_in[5];
    float* out = (float*)d_out;

    int n    = in_sizes[1];   // number of nodes (2M)
    int Lnum = in_sizes[3];   // number of instances (1M)

    {
        int tot = out_size > NBINS ? out_size : NBINS;
        int blocks = (tot + 255) / 256;
        zero_kernel<<<blocks, 256>>>(out, out_size);
    }
    {
        int blocks = (Lnum + 255) / 256;
        scatter_kernel<<<blocks, 256>>>(pos, nsx, nsy, lidx, ltype, Lnum, n);
    }
    {
        int blocks = (NBINS_XY + 255) / 256;
        compat_kernel<<<blocks, 256>>>(frac);
    }
    {
        int blocks = (Lnum + 255) / 256;
        gather_kernel<<<blocks, 256>>>(pos, nsx, nsy, lidx, ltype, out, Lnum, n);
    }
}

// round 3
// speedup vs baseline: 2.0798x; 2.0798x over previous
#include <cuda_runtime.h>

#define NBX 168
#define NBY 480
#define NBL 6
#define EXT 2
#define WW 5
#define NBYP 496                      // padded y stride (mult of 4)
#define PADY 8                        // y guard offset
#define PLANE (NBX * NBYP)            // 83328
#define NDEM (NBL * PLANE)            // 499968
#define INV_SQRT2 0.70710678118654752440f
#define INV_CAP (1.0f / 16.0f)

__device__ __align__(16) float g_dem[NDEM];
__device__ __align__(16) float g_compat[NDEM];

__device__ __forceinline__ void red_add_v4(float* addr, float a, float b,
                                           float c, float d) {
    asm volatile("red.global.add.v4.f32 [%0], {%1, %2, %3, %4};"
                 :: "l"(addr), "f"(a), "f"(b), "f"(c), "f"(d) : "memory");
}

// ---------------------------------------------------------------------------
// Phase 0: zero demand map + output buffer (compat pads stay 0 automatically)
// ---------------------------------------------------------------------------
__global__ void zero_kernel(float* __restrict__ out, int out_n) {
    int i = blockIdx.x * blockDim.x + threadIdx.x;
    if (i < NDEM) g_dem[i] = 0.0f;
    if (i < out_n) out[i] = 0.0f;
}

// 5-wide x-axis weights via erf chain (6 erfs), zeroed when bin out of range.
__device__ __forceinline__ void axis_weights_x(float c, int& b0, float* g) {
    b0 = (int)floorf(c) - EXT;
    float ep = erff(((float)b0 - c) * INV_SQRT2);
#pragma unroll
    for (int k = 0; k < WW; k++) {
        float e = erff(((float)(b0 + k + 1) - c) * INV_SQRT2);
        int b = b0 + k;
        g[k] = (b >= 0 && b < NBX) ? 0.5f * (e - ep) : 0.0f;
        ep = e;
    }
}

// 8-slot aligned y-axis window: slots y4..y4+7 (y4 = 4-aligned), weight zero
// outside the 5-wide truncation window or the [0,NBY) range. 9 erfs.
__device__ __forceinline__ void axis_weights_y8(float c, int& y4, float* w) {
    int b0 = (int)floorf(c) - EXT;
    y4 = b0 & ~3;
    float ep = erff(((float)y4 - c) * INV_SQRT2);
#pragma unroll
    for (int s = 0; s < 8; s++) {
        int y = y4 + s;
        float e = erff(((float)(y + 1) - c) * INV_SQRT2);
        bool ok = (y >= b0) && (y <= b0 + EXT + EXT) && (y >= 0) && (y < NBY);
        w[s] = ok ? 0.5f * (e - ep) : 0.0f;
        ep = e;
    }
}

// ---------------------------------------------------------------------------
// Phase 1: scatter-add area * (gX outer gY) via vector reductions
// ---------------------------------------------------------------------------
__global__ void scatter_kernel(const float* __restrict__ pos,
                               const float* __restrict__ nsx,
                               const float* __restrict__ nsy,
                               const int*   __restrict__ lidx,
                               const int*   __restrict__ ltype,
                               int Lnum, int n) {
    int l = blockIdx.x * blockDim.x + threadIdx.x;
    if (l >= Lnum) return;
    int idx = lidx[l];
    float sx = nsx[idx];
    float sy = nsy[idx];
    float cx = pos[idx]     + 0.5f * sx;
    float cy = pos[n + idx] + 0.5f * sy;
    float area = sx * sy;
    int lt = ltype[idx];

    int bx0, y4;
    float wx[WW], wy[8];
    axis_weights_x(cx, bx0, wx);
    axis_weights_y8(cy, y4, wy);

#pragma unroll
    for (int i = 0; i < WW; i++) {
        float axi = area * wx[i];
        if (axi == 0.0f) continue;
        float* p = g_dem + ((lt * NBX + (bx0 + i)) * NBYP + PADY + y4);
        red_add_v4(p,     axi * wy[0], axi * wy[1], axi * wy[2], axi * wy[3]);
        red_add_v4(p + 4, axi * wy[4], axi * wy[5], axi * wy[6], axi * wy[7]);
    }
}

// ---------------------------------------------------------------------------
// Phase 2: compat[t,x,y] = sum_l frac[t,l] * dem[l,x,y]  (runs over pads too;
// pads are zero in dem so compat pads come out zero)
// ---------------------------------------------------------------------------
__global__ void compat_kernel(const int* __restrict__ frac) {
    int p = blockIdx.x * blockDim.x + threadIdx.x;
    if (p >= PLANE) return;
    float d[NBL];
#pragma unroll
    for (int l = 0; l < NBL; l++) d[l] = g_dem[l * PLANE + p];
#pragma unroll
    for (int t = 0; t < NBL; t++) {
        float s = 0.0f;
#pragma unroll
        for (int l = 0; l < NBL; l++)
            s += (float)__ldg(&frac[t * NBL + l]) * d[l];
        g_compat[t * PLANE + p] = s;
    }
}

// ---------------------------------------------------------------------------
// Phase 3: gather compat under each window with 128-bit loads
// ---------------------------------------------------------------------------
__global__ void gather_kernel(const float* __restrict__ pos,
                              const float* __restrict__ nsx,
                              const float* __restrict__ nsy,
                              const int*   __restrict__ lidx,
                              const int*   __restrict__ ltype,
                              float* __restrict__ out,
                              int Lnum, int n) {
    int l = blockIdx.x * blockDim.x + threadIdx.x;
    if (l >= Lnum) return;
    int idx = lidx[l];
    float sx = nsx[idx];
    float sy = nsy[idx];
    float cx = pos[idx]     + 0.5f * sx;
    float cy = pos[n + idx] + 0.5f * sy;
    int lt = ltype[idx];

    int bx0, y4;
    float wx[WW], wy[8];
    axis_weights_x(cx, bx0, wx);
    axis_weights_y8(cy, y4, wy);

    float s = 0.0f;
#pragma unroll
    for (int i = 0; i < WW; i++) {
        if (wx[i] == 0.0f) continue;
        const float4* p = (const float4*)(g_compat +
                          ((lt * NBX + (bx0 + i)) * NBYP + PADY + y4));
        float4 a = p[0];
        float4 b = p[1];
        float sj = a.x * wy[0] + a.y * wy[1] + a.z * wy[2] + a.w * wy[3]
                 + b.x * wy[4] + b.y * wy[5] + b.z * wy[6] + b.w * wy[7];
        s += wx[i] * sj;
    }
    out[idx] = s * INV_CAP;
}

// ---------------------------------------------------------------------------
extern "C" void kernel_launch(void* const* d_in, const int* in_sizes, int n_in,
                              void* d_out, int out_size) {
    const float* pos   = (const float*)d_in[0];
    const float* nsx   = (const float*)d_in[1];
    const float* nsy   = (const float*)d_in[2];
    const int*   lidx  = (const int*)d_in[3];
    const int*   ltype = (const int*)d_in[4];
    const int*   frac  = (const int*)d_in[5];
    float* out = (float*)d_out;

    int n    = in_sizes[1];   // number of nodes (2M)
    int Lnum = in_sizes[3];   // number of instances (1M)

    {
        int tot = out_size > NDEM ? out_size : NDEM;
        zero_kernel<<<(tot + 255) / 256, 256>>>(out, out_size);
    }
    scatter_kernel<<<(Lnum + 255) / 256, 256>>>(pos, nsx, nsy, lidx, ltype,
                                                Lnum, n);
    compat_kernel<<<(PLANE + 255) / 256, 256>>>(frac);
    gather_kernel<<<(Lnum + 255) / 256, 256>>>(pos, nsx, nsy, lidx, ltype,
                                               out, Lnum, n);
}